// round 2
// baseline (speedup 1.0000x reference)
#include <cuda_runtime.h>
#include <cuda_bf16.h>
#include <cstdint>

#define Nn   32
#define CIN  64
#define COUT 128
#define Vv   25
#define Tlen 300
#define Ss   3
#define VT   7500
#define VV   625
#define EPSf 1e-5f

typedef unsigned long long u64;

// device scratch (allocation-free per harness rules)
__device__ float g_feat[Ss * Nn * COUT * VT]; // [s][n][o][w*300+t]  (368.6 MB)
__device__ float g_A[Ss * Nn * COUT * VV];    // [s][n][o][v*25+w]   (30.7 MB)

__device__ __forceinline__ void fma2(u64& d, u64 a, u64 b) {
    asm("fma.rn.f32x2 %0, %1, %2, %0;" : "+l"(d) : "l"(a), "l"(b));
}
__device__ __forceinline__ u64 dup2(float v) {
    u64 r; asm("mov.b64 %0, {%1, %1};" : "=l"(r) : "f"(v)); return r;
}
__device__ __forceinline__ u64 pack2(float lo, float hi) {
    u64 r; asm("mov.b64 %0, {%1, %2};" : "=l"(r) : "f"(lo), "f"(hi)); return r;
}
__device__ __forceinline__ float lo32(u64 v) { return __uint_as_float((unsigned)v); }
__device__ __forceinline__ float hi32(u64 v) { return __uint_as_float((unsigned)(v >> 32)); }

// ---------------------------------------------------------------------------
// Kernel A: g_A[s][n][o][v,w] = (sum_i ada_w[s,o,i]*ada_A[n,i,v,w] + ada_b[s,o]) * PA[s,v,w]
// grid (5 vw-chunks of 125, n, s), 128 threads
// ---------------------------------------------------------------------------
__global__ void kA(const float* __restrict__ adaA, const float* __restrict__ PA,
                   const float* __restrict__ ada_w, const float* __restrict__ ada_b) {
    __shared__ float wsm[COUT * CIN]; // 32 KB
    __shared__ float bsm[COUT];
    int tid = threadIdx.x;
    int s = blockIdx.z, n = blockIdx.y;
    int vw0 = blockIdx.x * 125;

    for (int idx = tid; idx < COUT * CIN; idx += 128)
        wsm[idx] = ada_w[s * COUT * CIN + idx];
    if (tid < COUT) bsm[tid] = ada_b[s * COUT + tid];
    __syncthreads();
    if (tid >= 125) return;

    int vw = vw0 + tid;
    float areg[CIN];
#pragma unroll
    for (int i = 0; i < CIN; i++) areg[i] = adaA[(n * CIN + i) * VV + vw];
    float pa = PA[s * VV + vw];
    float* outp = g_A + (size_t)((s * Nn + n) * COUT) * VV + vw;

    for (int o = 0; o < COUT; o += 4) {
        float a0 = bsm[o], a1 = bsm[o + 1], a2 = bsm[o + 2], a3 = bsm[o + 3];
        const float* w0 = wsm + o * CIN;
#pragma unroll
        for (int i = 0; i < CIN; i += 4) {
            float4 wa = *(const float4*)(w0 + i);
            float4 wb = *(const float4*)(w0 + CIN + i);
            float4 wc = *(const float4*)(w0 + 2 * CIN + i);
            float4 wd = *(const float4*)(w0 + 3 * CIN + i);
            a0 = fmaf(wa.x, areg[i], a0); a0 = fmaf(wa.y, areg[i+1], a0);
            a0 = fmaf(wa.z, areg[i+2], a0); a0 = fmaf(wa.w, areg[i+3], a0);
            a1 = fmaf(wb.x, areg[i], a1); a1 = fmaf(wb.y, areg[i+1], a1);
            a1 = fmaf(wb.z, areg[i+2], a1); a1 = fmaf(wb.w, areg[i+3], a1);
            a2 = fmaf(wc.x, areg[i], a2); a2 = fmaf(wc.y, areg[i+1], a2);
            a2 = fmaf(wc.z, areg[i+2], a2); a2 = fmaf(wc.w, areg[i+3], a2);
            a3 = fmaf(wd.x, areg[i], a3); a3 = fmaf(wd.y, areg[i+1], a3);
            a3 = fmaf(wd.z, areg[i+2], a3); a3 = fmaf(wd.w, areg[i+3], a3);
        }
        outp[(size_t)(o + 0) * VV] = a0 * pa;
        outp[(size_t)(o + 1) * VV] = a1 * pa;
        outp[(size_t)(o + 2) * VV] = a2 * pa;
        outp[(size_t)(o + 3) * VV] = a3 * pa;
    }
}

// ---------------------------------------------------------------------------
// Kernel B: per-n GEMM C[512 x 7500] = W[512 x 64] @ x[n][64 x 7500]
//   rows [0,384): feat (s=r>>7, o=r&127) + conv3_b  -> g_feat
//   rows [384,512): residual, down-BN folded        -> d_out
// FMA2 inner loop; W packed as row-pair u64 in smem.
// grid (59 col-tiles of 128, 8 row-tiles of 64, n=32), 256 threads.
// ---------------------------------------------------------------------------
#define KB_SMEM (64 * 32 * 8 + 64 * 128 * 4)  // Ws 16KB + Xs 32KB = 49152
__global__ void __launch_bounds__(256)
kB(const float* __restrict__ x,
   const float* __restrict__ conv3_w, const float* __restrict__ conv3_b,
   const float* __restrict__ down_w,  const float* __restrict__ down_b,
   const float* __restrict__ dg, const float* __restrict__ dbeta,
   const float* __restrict__ dm, const float* __restrict__ dvar,
   float* __restrict__ res_out) {
    extern __shared__ char smemB[];
    u64*   Ws = (u64*)smemB;               // [k=64][rowpair=32]
    float* Xs = (float*)(smemB + 64 * 32 * 8); // [k=64][c=128]

    int tid = threadIdx.x;
    int n  = blockIdx.z;
    int r0 = blockIdx.y * 64;
    int c0 = blockIdx.x * 128;
    int ncols = VT - c0; if (ncols > 128) ncols = 128; // 128 or 76

    // stage W (row pairs, dbn-scale folded into residual rows)
    for (int idx = tid; idx < 64 * 32; idx += 256) {
        int k = idx >> 5, rp = idx & 31;
        int r = r0 + 2 * rp;
        float w0, w1;
        if (r < Ss * COUT) {
            w0 = conv3_w[r * CIN + k];
            w1 = conv3_w[(r + 1) * CIN + k];
        } else {
            int o = r - Ss * COUT;
            float s0 = dg[o]     * rsqrtf(dvar[o]     + EPSf);
            float s1 = dg[o + 1] * rsqrtf(dvar[o + 1] + EPSf);
            w0 = s0 * down_w[o * CIN + k];
            w1 = s1 * down_w[(o + 1) * CIN + k];
        }
        Ws[k * 32 + rp] = pack2(w0, w1);
    }
    // stage X
    for (int idx = tid; idx < 64 * 32; idx += 256) {
        int k = idx >> 5, c4 = (idx & 31) << 2;
        float4 val = make_float4(0.f, 0.f, 0.f, 0.f);
        if (c4 < ncols) val = *(const float4*)(x + (size_t)(n * CIN + k) * VT + c0 + c4);
        *(float4*)(Xs + k * 128 + c4) = val;
    }
    __syncthreads();

    int tx = tid & 31, ty = tid >> 5; // 4 cols (tx*4..), 8 rows (ty*8..)
    u64 acc[4][4];
#pragma unroll
    for (int i = 0; i < 4; i++)
#pragma unroll
        for (int j = 0; j < 4; j++) acc[i][j] = 0ull;

#pragma unroll 4
    for (int k = 0; k < CIN; k++) {
        float4 xv = *(const float4*)(Xs + k * 128 + tx * 4);
        u64 x0 = dup2(xv.x), x1 = dup2(xv.y), x2 = dup2(xv.z), x3 = dup2(xv.w);
        ulonglong2 wA = *(const ulonglong2*)(Ws + k * 32 + ty * 4);
        ulonglong2 wB = *(const ulonglong2*)(Ws + k * 32 + ty * 4 + 2);
        fma2(acc[0][0], wA.x, x0); fma2(acc[0][1], wA.x, x1);
        fma2(acc[0][2], wA.x, x2); fma2(acc[0][3], wA.x, x3);
        fma2(acc[1][0], wA.y, x0); fma2(acc[1][1], wA.y, x1);
        fma2(acc[1][2], wA.y, x2); fma2(acc[1][3], wA.y, x3);
        fma2(acc[2][0], wB.x, x0); fma2(acc[2][1], wB.x, x1);
        fma2(acc[2][2], wB.x, x2); fma2(acc[2][3], wB.x, x3);
        fma2(acc[3][0], wB.y, x0); fma2(acc[3][1], wB.y, x1);
        fma2(acc[3][2], wB.y, x2); fma2(acc[3][3], wB.y, x3);
    }

    if (tx * 4 < ncols) {
        int col = c0 + tx * 4;
#pragma unroll
        for (int j = 0; j < 8; j++) {
            int r = r0 + ty * 8 + j;
            int rp = j >> 1;
            float v0, v1, v2, v3;
            if (j & 1) {
                v0 = hi32(acc[rp][0]); v1 = hi32(acc[rp][1]);
                v2 = hi32(acc[rp][2]); v3 = hi32(acc[rp][3]);
            } else {
                v0 = lo32(acc[rp][0]); v1 = lo32(acc[rp][1]);
                v2 = lo32(acc[rp][2]); v3 = lo32(acc[rp][3]);
            }
            float bias; float* dst;
            if (r < Ss * COUT) {
                bias = conv3_b[r];
                dst = g_feat + (size_t)(((r >> 7) * Nn + n) * COUT + (r & 127)) * VT + col;
            } else {
                int o = r - Ss * COUT;
                float sc = dg[o] * rsqrtf(dvar[o] + EPSf);
                bias = sc * (down_b[o] - dm[o]) + dbeta[o];
                dst = res_out + (size_t)(n * COUT + o) * VT + col;
            }
            float4 w = make_float4(v0 + bias, v1 + bias, v2 + bias, v3 + bias);
            *(float4*)dst = w;
        }
    }
}

// ---------------------------------------------------------------------------
// Kernel C: out[n,o,v,t] = relu( bn(sum_{s,w} A[s,n,o,v,w]*feat[s,n,o,w,t]) + res )
// block = (o, n), 320 threads (300 compute, one t each, 13 v-pairs via FMA2)
// ---------------------------------------------------------------------------
#define KC_SMEM (75 * 300 * 4 + 75 * 14 * 8)  // feat 90000 + A2 8400 = 98400
__global__ void __launch_bounds__(320)
kC(const float* __restrict__ bn_g, const float* __restrict__ bn_b,
   const float* __restrict__ bn_m, const float* __restrict__ bn_v,
   float* __restrict__ out) {
    extern __shared__ char smemC[];
    float* feat_s = (float*)smemC;               // [sw=75][t=300]
    u64*   A2     = (u64*)(smemC + 75 * 300 * 4); // [sw=75][vp=14] (13 used, pad)

    int tid = threadIdx.x;
    int o = blockIdx.x, n = blockIdx.y;

    // stage feat tile: 75 rows x 300 t
    const size_t fb = (size_t)n * COUT + o;
    for (int idx = tid; idx < 75 * 75; idx += 320) {
        int row = idx / 75, c4 = (idx % 75) * 4;
        int s = row / 25, w = row % 25;
        float4 val = *(const float4*)(g_feat + (size_t)((s * Nn + n) * COUT + o) * VT + w * Tlen + c4);
        *(float4*)(feat_s + row * 300 + c4) = val;
    }
    // stage A, packed as v-pairs (v padded 25 -> 26 with zero)
    for (int idx = tid; idx < 75 * 13; idx += 320) {
        int sw = idx / 13, vp = idx % 13;
        int s = sw / 25, w = sw % 25;
        const float* ap = g_A + (size_t)((s * Nn + n) * COUT + o) * VV + w;
        float a0 = ap[(2 * vp) * Vv];
        float a1 = (2 * vp + 1 < Vv) ? ap[(2 * vp + 1) * Vv] : 0.f;
        A2[sw * 14 + vp] = pack2(a0, a1);
    }
    __syncthreads();

    if (tid < Tlen) {
        int t = tid;
        u64 acc[13];
#pragma unroll
        for (int i = 0; i < 13; i++) acc[i] = 0ull;

#pragma unroll 3
        for (int sw = 0; sw < 75; sw++) {
            u64 f2 = dup2(feat_s[sw * 300 + t]);
            const ulonglong2* ar = (const ulonglong2*)(A2 + sw * 14);
#pragma unroll
            for (int j = 0; j < 6; j++) {
                ulonglong2 a = ar[j];
                fma2(acc[2 * j],     a.x, f2);
                fma2(acc[2 * j + 1], a.y, f2);
            }
            fma2(acc[12], A2[sw * 14 + 12], f2);
        }

        float sc = bn_g[o] * rsqrtf(bn_v[o] + EPSf);
        float sh = bn_b[o] - bn_m[o] * sc;
        float* op = out + ((size_t)n * COUT + o) * VT + t;
#pragma unroll
        for (int vp = 0; vp < 13; vp++) {
            int v0 = 2 * vp;
            float r0 = op[v0 * Tlen];
            op[v0 * Tlen] = fmaxf(fmaf(lo32(acc[vp]), sc, sh) + r0, 0.f);
            if (v0 + 1 < Vv) {
                float r1 = op[(v0 + 1) * Tlen];
                op[(v0 + 1) * Tlen] = fmaxf(fmaf(hi32(acc[vp]), sc, sh) + r1, 0.f);
            }
        }
    }
}

// ---------------------------------------------------------------------------
extern "C" void kernel_launch(void* const* d_in, const int* in_sizes, int n_in,
                              void* d_out, int out_size) {
    const float* x       = (const float*)d_in[0];
    const float* ada_A   = (const float*)d_in[1];
    const float* PA      = (const float*)d_in[2];
    const float* conv3_w = (const float*)d_in[3];
    const float* conv3_b = (const float*)d_in[4];
    const float* ada_w   = (const float*)d_in[5];
    const float* ada_b   = (const float*)d_in[6];
    const float* bn_g    = (const float*)d_in[7];
    const float* bn_b    = (const float*)d_in[8];
    const float* bn_m    = (const float*)d_in[9];
    const float* bn_v    = (const float*)d_in[10];
    const float* down_w  = (const float*)d_in[11];
    const float* down_b  = (const float*)d_in[12];
    const float* dbn_g   = (const float*)d_in[13];
    const float* dbn_b   = (const float*)d_in[14];
    const float* dbn_m   = (const float*)d_in[15];
    const float* dbn_v   = (const float*)d_in[16];
    float* out = (float*)d_out;

    cudaFuncSetAttribute(kB, cudaFuncAttributeMaxDynamicSharedMemorySize, KB_SMEM);
    cudaFuncSetAttribute(kC, cudaFuncAttributeMaxDynamicSharedMemorySize, KC_SMEM);

    kA<<<dim3(5, Nn, Ss), 128>>>(ada_A, PA, ada_w, ada_b);
    kB<<<dim3(59, 8, Nn), 256, KB_SMEM>>>(x, conv3_w, conv3_b, down_w, down_b,
                                          dbn_g, dbn_b, dbn_m, dbn_v, out);
    kC<<<dim3(COUT, Nn), 320, KC_SMEM>>>(bn_g, bn_b, bn_m, bn_v, out);
}